// round 11
// baseline (speedup 1.0000x reference)
#include <cuda_runtime.h>

#define NPTS 32768

// ---------------------------------------------------------------------------
// Scratch: per-net optical depth tau[g][n]  (nets 7,8 are dead -> never written
// or read, but keep full 76 stride for simple indexing).
// ---------------------------------------------------------------------------
__device__ float g_tau[76 * NPTS];

// Active nets (h2o nets 7 and 8 are never referenced by H2O_IDX -> dead code).
__constant__ int c_net_id[74] = {
    0, 1, 2, 3, 4, 5, 6,
    9, 10, 11, 12, 13, 14, 15, 16, 17, 18, 19, 20, 21, 22, 23, 24, 25, 26, 27, 28,
    29, 30, 31, 32, 33, 34, 35, 36, 37, 38, 39, 40, 41,
    42, 43, 44, 45, 46, 47, 48, 49, 50,
    51, 52, 53,
    54, 55, 56, 57, 58, 59, 60, 61, 62,
    63, 64, 65, 66, 67, 68, 69, 70, 71, 72, 73, 74, 75
};

// Per-channel contributing nets (gather form of the reference scatter-adds),
// in the same accumulation order as the reference: h2o, o3, co2, n2o, ch4, u.
__constant__ int c_ch_cnt[29] = {
    6, 6, 6, 2, 2, 2, 2, 2, 2, 2, 2, 2, 2, 2, 2, 2, 2,
    3, 3, 3, 3, 3, 3, 1, 1, 2, 2, 3, 3
};
__constant__ int c_ch_nets[29][6] = {
    {0, 29, 42, 51, 54, 63}, {1, 30, 43, 52, 55, 64}, {2, 31, 44, 53, 56, 65},
    {3, 57, 0, 0, 0, 0},  {4, 58, 0, 0, 0, 0},  {5, 45, 0, 0, 0, 0},
    {6, 46, 0, 0, 0, 0},  {3, 59, 0, 0, 0, 0},  {4, 60, 0, 0, 0, 0},
    {9, 47, 0, 0, 0, 0},  {10, 48, 0, 0, 0, 0}, {11, 61, 0, 0, 0, 0},
    {12, 62, 0, 0, 0, 0}, {13, 49, 0, 0, 0, 0}, {14, 50, 0, 0, 0, 0},
    {15, 66, 0, 0, 0, 0}, {16, 67, 0, 0, 0, 0},
    {17, 32, 68, 0, 0, 0}, {18, 33, 69, 0, 0, 0}, {19, 34, 70, 0, 0, 0},
    {20, 35, 71, 0, 0, 0}, {21, 36, 72, 0, 0, 0}, {22, 37, 73, 0, 0, 0},
    {23, 0, 0, 0, 0, 0},  {24, 0, 0, 0, 0, 0},
    {25, 38, 0, 0, 0, 0}, {26, 39, 0, 0, 0, 0},
    {27, 40, 74, 0, 0, 0}, {28, 41, 75, 0, 0, 0}
};

// ---------------------------------------------------------------------------
// Packed fp32x2 helpers (Blackwell f32x2 path: 2 IEEE fp32 FMAs per issue).
// ---------------------------------------------------------------------------
__device__ __forceinline__ unsigned long long pack2(float lo, float hi) {
    unsigned long long r;
    asm("mov.b64 %0, {%1, %2};" : "=l"(r) : "f"(lo), "f"(hi));
    return r;
}
__device__ __forceinline__ void fma2(unsigned long long& d,
                                     unsigned long long a,
                                     unsigned long long b) {
    asm("fma.rn.f32x2 %0, %1, %2, %0;" : "+l"(d) : "l"(a), "l"(b));
}
__device__ __forceinline__ float2 unpack2(unsigned long long v) {
    float2 f;
    asm("mov.b64 {%0, %1}, %2;" : "=f"(f.x), "=f"(f.y) : "l"(v));
    return f;
}

// ---------------------------------------------------------------------------
// Pass 1: per-(net, point) fused MLP -> tau[g][n]
//   block = 128 threads, 1 point/thread; grid = (NPTS/128, 74)
//   W2[g] (64x64 fp32, 16 KB) staged in SMEM; 32 packed k-accumulators in regs;
//   h1[j] recomputed on the fly from broadcast SMEM (saves 64 regs).
// ---------------------------------------------------------------------------
__global__ __launch_bounds__(128, 3)
void mlp_tau_kernel(const float* __restrict__ t_p,
                    const float* __restrict__ comp,
                    const float* __restrict__ W1,
                    const float* __restrict__ b1,
                    const float* __restrict__ W2,
                    const float* __restrict__ b2,
                    const float* __restrict__ Wout,
                    const float* __restrict__ bout)
{
    __shared__ __align__(16) float sW2[64 * 64];
    __shared__ float sW1[128];
    __shared__ float sb1[64];
    __shared__ float sb2[64];
    __shared__ float swout[64];

    const int tid = threadIdx.x;
    const int g = c_net_id[blockIdx.y];

    // Stage weights for this net.
    {
        const float4* src = reinterpret_cast<const float4*>(W2 + g * 4096);
        float4* dst = reinterpret_cast<float4*>(sW2);
        #pragma unroll
        for (int i = 0; i < 8; i++) dst[tid + 128 * i] = src[tid + 128 * i];
        sW1[tid] = W1[g * 128 + tid];
        if (tid < 64) {
            sb1[tid]   = b1[g * 64 + tid];
            sb2[tid]   = b2[g * 64 + tid];
            swout[tid] = Wout[g * 64 + tid];
        }
    }
    __syncthreads();

    const int n = blockIdx.x * 128 + tid;
    const float2 t = reinterpret_cast<const float2*>(t_p)[n];

    // 32 packed accumulators over output-neuron pairs (k, k+1), init with b2.
    unsigned long long acc[32];
    #pragma unroll
    for (int kk = 0; kk < 32; kk++)
        acc[kk] = pack2(sb2[2 * kk], sb2[2 * kk + 1]);

    const ulonglong2* __restrict__ w2v = reinterpret_cast<const ulonglong2*>(sW2);

    // Main loop: for each hidden unit j, recompute h1[j], then rank-1 update
    // of all 64 layer-2 accumulators (32 packed FMA2 via broadcast LDS.128).
    #pragma unroll 4
    for (int j = 0; j < 64; j++) {
        float h = fmaf(t.x, sW1[j], fmaf(t.y, sW1[64 + j], sb1[j]));
        h = fmaxf(h, 0.0f);
        const unsigned long long hj = pack2(h, h);
        const ulonglong2* r = w2v + j * 16;
        #pragma unroll
        for (int q = 0; q < 16; q++) {
            ulonglong2 w = r[q];
            fma2(acc[2 * q],     hj, w.x);
            fma2(acc[2 * q + 1], hj, w.y);
        }
    }

    // Layer 3: ke = relu( sum_k relu(acc_k) * Wout_k + bout ), 4 partial chains.
    float ke0 = 0.f, ke1 = 0.f, ke2 = 0.f, ke3 = 0.f;
    #pragma unroll
    for (int kk = 0; kk < 32; kk++) {
        float2 a = unpack2(acc[kk]);
        a.x = fmaxf(a.x, 0.0f);
        a.y = fmaxf(a.y, 0.0f);
        if (kk & 1) {
            ke2 = fmaf(a.x, swout[2 * kk], ke2);
            ke3 = fmaf(a.y, swout[2 * kk + 1], ke3);
        } else {
            ke0 = fmaf(a.x, swout[2 * kk], ke0);
            ke1 = fmaf(a.y, swout[2 * kk + 1], ke1);
        }
    }
    const float ke = fmaxf((ke0 + ke2) + (ke1 + ke3) + bout[g], 0.0f);

    // COMP_IDX(g): repeat(arange(6), [29,13,9,3,9,13])
    const int cg = (g < 29) ? 0 : (g < 42) ? 1 : (g < 51) ? 2
                 : (g < 54) ? 3 : (g < 63) ? 4 : 5;

    g_tau[g * NPTS + n] = ke * comp[cg * NPTS + n];
}

// ---------------------------------------------------------------------------
// Pass 2: gather per-channel net contributions + the two broadcast products.
// Output layout: [tau_gases(29,N) | tau_lw(29,N) | tau_iw(29,N)]  fp32.
// ---------------------------------------------------------------------------
__global__ void combine_kernel(const float* __restrict__ comp,
                               const float* __restrict__ ke_lw,
                               const float* __restrict__ ke_iw,
                               float* __restrict__ out)
{
    const int c = blockIdx.y;
    const int n = blockIdx.x * blockDim.x + threadIdx.x;

    const int cnt = c_ch_cnt[c];
    float s = 0.0f;
    #pragma unroll
    for (int i = 0; i < 6; i++)
        if (i < cnt) s += g_tau[c_ch_nets[c][i] * NPTS + n];

    out[c * NPTS + n] = s;
    out[29 * NPTS + c * NPTS + n] = ke_lw[c] * comp[6 * NPTS + n];
    out[58 * NPTS + c * NPTS + n] = ke_iw[c] * comp[7 * NPTS + n];
}

// ---------------------------------------------------------------------------
// Launch contract
// ---------------------------------------------------------------------------
extern "C" void kernel_launch(void* const* d_in, const int* in_sizes, int n_in,
                              void* d_out, int out_size)
{
    const float* t_p   = (const float*)d_in[0];
    const float* comp  = (const float*)d_in[1];
    const float* W1    = (const float*)d_in[2];
    const float* b1    = (const float*)d_in[3];
    const float* W2    = (const float*)d_in[4];
    const float* b2    = (const float*)d_in[5];
    const float* Wout  = (const float*)d_in[6];
    const float* bout  = (const float*)d_in[7];
    const float* ke_lw = (const float*)d_in[8];
    const float* ke_iw = (const float*)d_in[9];
    float* out = (float*)d_out;

    dim3 grid1(NPTS / 128, 74);
    mlp_tau_kernel<<<grid1, 128>>>(t_p, comp, W1, b1, W2, b2, Wout, bout);

    dim3 grid2(NPTS / 256, 29);
    combine_kernel<<<grid2, 256>>>(comp, ke_lw, ke_iw, out);
}